// round 3
// baseline (speedup 1.0000x reference)
#include <cuda_runtime.h>
#include <cstdint>
#include <math.h>

// PatchRepulsionLoss: pcs [8192, 2048, 3] f32 -> scalar f32
// B=8192, P=32 patches, n=64 pts/patch, N_SIGMA=1
// loss = sum_b sum_{i<=j} || relu(std_i+std_j - |mean_i-mean_j|) ||_2 / (528*B)
//
// Persistent-CTA design: grid = 148*8 CTAs, each streams multiple batches
// through a 2-stage TMA ring of 12KB chunks (16 patches per chunk).

#define NPATCH 32
#define NBATCH 8192
#define NTHREADS 256
#define GRIDSZ (148 * 8)
#define CHUNK_BYTES 12288            // 16 patches * 64 pts * 3 * 4B
#define CHUNK_F4 (CHUNK_BYTES / 16)  // 768 float4
#define BATCH_BYTES (2 * CHUNK_BYTES)

__global__ void prl_zero_kernel(float* out) { out[0] = 0.0f; }

__device__ __forceinline__ uint32_t smem_u32(const void* p) {
    uint32_t a;
    asm("{ .reg .u64 t; cvta.to.shared.u64 t, %1; cvt.u32.u64 %0, t; }"
        : "=r"(a) : "l"(p));
    return a;
}

__device__ __forceinline__ void bulk_copy(uint32_t dst, const void* src,
                                          uint32_t bytes, uint32_t mbar) {
    asm volatile("mbarrier.arrive.expect_tx.shared.b64 _, [%0], %1;"
                 :: "r"(mbar), "r"(bytes) : "memory");
    asm volatile(
        "cp.async.bulk.shared::cta.global.mbarrier::complete_tx::bytes "
        "[%0], [%1], %2, [%3];"
        :: "r"(dst), "l"(src), "r"(bytes), "r"(mbar) : "memory");
}

__device__ __forceinline__ void mbar_wait(uint32_t mbar, uint32_t parity) {
    uint32_t done;
    asm volatile(
        "{\n\t.reg .pred p;\n\t"
        "mbarrier.try_wait.parity.acquire.cta.shared::cta.b64 p, [%1], %2;\n\t"
        "selp.b32 %0, 1, 0, p;\n\t}"
        : "=r"(done) : "r"(mbar), "r"(parity) : "memory");
    if (!done) {
        asm volatile(
            "{\n\t.reg .pred P1;\n\t"
            "WL_%=:\n\t"
            "mbarrier.try_wait.parity.acquire.cta.shared::cta.b64 P1, [%0], %1, 0x989680;\n\t"
            "@P1 bra.uni WD_%=;\n\t"
            "bra.uni WL_%=;\n\t"
            "WD_%=:\n\t}"
            :: "r"(mbar), "r"(parity) : "memory");
    }
}

// Per-chunk stats: 16 patches, 16 threads/patch, 3 float4 (4 points)/thread.
// Conflict-free LDS.128; dim phase handled via w-rotated accumulator frame.
__device__ __forceinline__ void chunk_stats(const float4* __restrict__ buf,
                                            int tid, int half,
                                            float* __restrict__ s_mean,
                                            float* __restrict__ s_std) {
    const int p = tid >> 4;      // chunk-local patch 0..15
    const int w = tid & 15;      // within-patch thread 0..15
    const int w3 = w % 3;        // frame rotation

    float a0 = 0.f, a1 = 0.f, a2 = 0.f;   // frame sums
    float g0 = 0.f, g1 = 0.f, g2 = 0.f;   // frame sumsq
    const float4* base = buf + p * 48 + w;
#pragma unroll
    for (int k = 0; k < 3; k++) {
        float4 v = base[16 * k];
        float t0 = v.x + v.w;
        float t1 = v.y;
        float t2 = v.z;
        float u0 = fmaf(v.x, v.x, v.w * v.w);
        float u1 = v.y * v.y;
        float u2 = v.z * v.z;
        // frame start-dim = k (compile-time rotation)
        if (k == 0) { a0 += t0; a1 += t1; a2 += t2; g0 += u0; g1 += u1; g2 += u2; }
        if (k == 1) { a1 += t0; a2 += t1; a0 += t2; g1 += u0; g2 += u1; g0 += u2; }
        if (k == 2) { a2 += t0; a0 += t1; a1 += t2; g2 += u0; g0 += u1; g1 += u2; }
    }
    // Un-rotate: actual dim d = frame[(d - w3) mod 3]
    float s0 = (w3 == 0) ? a0 : (w3 == 1) ? a2 : a1;
    float s1 = (w3 == 0) ? a1 : (w3 == 1) ? a0 : a2;
    float s2 = (w3 == 0) ? a2 : (w3 == 1) ? a1 : a0;
    float q0 = (w3 == 0) ? g0 : (w3 == 1) ? g2 : g1;
    float q1 = (w3 == 0) ? g1 : (w3 == 1) ? g0 : g2;
    float q2 = (w3 == 0) ? g2 : (w3 == 1) ? g1 : g0;

    // 16-lane group reduce (lanes [0..15],[16..31] aligned)
#pragma unroll
    for (int off = 8; off; off >>= 1) {
        s0 += __shfl_xor_sync(0xFFFFFFFFu, s0, off);
        s1 += __shfl_xor_sync(0xFFFFFFFFu, s1, off);
        s2 += __shfl_xor_sync(0xFFFFFFFFu, s2, off);
        q0 += __shfl_xor_sync(0xFFFFFFFFu, q0, off);
        q1 += __shfl_xor_sync(0xFFFFFFFFu, q1, off);
        q2 += __shfl_xor_sync(0xFFFFFFFFu, q2, off);
    }
    if (w == 0) {
        const int gp = half * 16 + p;
        const float inv_n = 1.0f / 64.0f;
        const float inv_nm1 = 1.0f / 63.0f;
        s_mean[gp * 3 + 0] = s0 * inv_n;
        s_mean[gp * 3 + 1] = s1 * inv_n;
        s_mean[gp * 3 + 2] = s2 * inv_n;
        float v0 = (q0 - s0 * s0 * inv_n) * inv_nm1;
        float v1 = (q1 - s1 * s1 * inv_n) * inv_nm1;
        float v2 = (q2 - s2 * s2 * inv_n) * inv_nm1;
        s_std[gp * 3 + 0] = sqrtf(fmaxf(v0, 0.0f));
        s_std[gp * 3 + 1] = sqrtf(fmaxf(v1, 0.0f));
        s_std[gp * 3 + 2] = sqrtf(fmaxf(v2, 0.0f));
    }
}

__global__ void __launch_bounds__(NTHREADS, 8)
prl_main_kernel(const float* __restrict__ pcs, float* __restrict__ out) {
    __shared__ alignas(128) float4 sbuf[2][CHUNK_F4];   // 2 x 12 KB
    __shared__ alignas(8) uint64_t mbar[2];
    __shared__ float s_mean[NPATCH * 3];
    __shared__ float s_std[NPATCH * 3];
    __shared__ float s_part[8];

    const int tid = threadIdx.x;
    const int lane = tid & 31;
    const int warp = tid >> 5;
    const uint32_t mb0 = smem_u32(&mbar[0]);
    const uint32_t mb1 = smem_u32(&mbar[1]);
    const uint32_t db0 = smem_u32(&sbuf[0][0]);
    const uint32_t db1 = smem_u32(&sbuf[1][0]);

    if (tid == 0) {
        asm volatile("mbarrier.init.shared.b64 [%0], 1;" :: "r"(mb0) : "memory");
        asm volatile("mbarrier.init.shared.b64 [%0], 1;" :: "r"(mb1) : "memory");
    }
    __syncthreads();

    const char* pbase = reinterpret_cast<const char*>(pcs);
    int b = blockIdx.x;
    const int stride = gridDim.x;

    // Prologue: prefetch both halves of first batch
    if (tid == 0 && b < NBATCH) {
        bulk_copy(db0, pbase + (size_t)b * BATCH_BYTES, CHUNK_BYTES, mb0);
        bulk_copy(db1, pbase + (size_t)b * BATCH_BYTES + CHUNK_BYTES,
                  CHUNK_BYTES, mb1);
    }

    uint32_t ph0 = 0, ph1 = 0;
    float cta_acc = 0.0f;

    for (; b < NBATCH; b += stride) {
        const int bn = b + stride;
        const bool more = (bn < NBATCH);

        // --- chunk 0 (patches 0..15) ---
        mbar_wait(mb0, ph0); ph0 ^= 1;
        chunk_stats(sbuf[0], tid, 0, s_mean, s_std);
        __syncthreads();   // buf0 reads done, s_mean[0..16) visible
        if (tid == 0 && more)
            bulk_copy(db0, pbase + (size_t)bn * BATCH_BYTES, CHUNK_BYTES, mb0);

        // --- chunk 1 (patches 16..31) ---
        mbar_wait(mb1, ph1); ph1 ^= 1;
        chunk_stats(sbuf[1], tid, 1, s_mean, s_std);
        __syncthreads();   // buf1 reads done, s_mean[16..32) visible
        if (tid == 0 && more)
            bulk_copy(db1, pbase + (size_t)bn * BATCH_BYTES + CHUNK_BYTES,
                      CHUNK_BYTES, mb1);

        // --- pair phase: upper-tri incl diag = 0.5*full + 0.5*diag ---
        float local = 0.0f;
#pragma unroll
        for (int k = 0; k < (NPATCH * NPATCH) / NTHREADS; k++) {
            const int id = tid + k * NTHREADS;
            const int i = id >> 5;   // uniform within warp (broadcast)
            const int j = id & 31;   // stride-3 words, conflict-free
            float acc = 0.0f;
#pragma unroll
            for (int d = 0; d < 3; d++) {
                float ssum = s_std[i * 3 + d] + s_std[j * 3 + d];
                float delta = fabsf(s_mean[i * 3 + d] - s_mean[j * 3 + d]);
                float rep = fmaxf(ssum - delta, 0.0f);
                acc = fmaf(rep, rep, acc);
            }
            float nrm = sqrtf(acc);
            local += (i == j) ? nrm : 0.5f * nrm;
        }

        // --- block reduce into cta_acc (held at warp0/lane0) ---
#pragma unroll
        for (int off = 16; off; off >>= 1)
            local += __shfl_xor_sync(0xFFFFFFFFu, local, off);
        if (lane == 0) s_part[warp] = local;
        __syncthreads();
        if (warp == 0) {
            float v = (lane < 8) ? s_part[lane] : 0.0f;
#pragma unroll
            for (int off = 4; off; off >>= 1)
                v += __shfl_xor_sync(0xFFFFFFFFu, v, off);
            if (lane == 0) cta_acc += v;
        }
        __syncthreads();   // s_part reads done before next batch reuses it
    }

    if (tid == 0 && cta_acc != 0.0f) {
        const float scale = 1.0f / (528.0f * (float)NBATCH);
        atomicAdd(out, cta_acc * scale);
    }
    // note: cta_acc==0 only when loss contribution is exactly 0; skipping the
    // atomic then is still correct (adds nothing).
}

extern "C" void kernel_launch(void* const* d_in, const int* in_sizes, int n_in,
                              void* d_out, int out_size) {
    const float* pcs = (const float*)d_in[0];
    float* out = (float*)d_out;
    prl_zero_kernel<<<1, 1>>>(out);
    prl_main_kernel<<<GRIDSZ, NTHREADS>>>(pcs, out);
}

// round 4
// speedup vs baseline: 1.2472x; 1.2472x over previous
#include <cuda_runtime.h>
#include <cstdint>
#include <math.h>

// PatchRepulsionLoss: pcs [8192, 2048, 3] f32 -> scalar f32
// B=8192, P=32 patches, n=64 pts/patch, N_SIGMA=1
// loss = sum_b sum_{i<=j} || relu(std_i+std_j - |mean_i-mean_j|) ||_2 / (528*B)

#define NPATCH 32
#define NBATCH 8192
#define NTHREADS 256
#define CHUNK_BYTES 12288            // 16 patches
#define BATCH_BYTES (2 * CHUNK_BYTES)

__global__ void prl_zero_kernel(float* out) { out[0] = 0.0f; }

__device__ __forceinline__ uint32_t smem_u32(const void* p) {
    uint32_t a;
    asm("{ .reg .u64 t; cvta.to.shared.u64 t, %1; cvt.u32.u64 %0, t; }"
        : "=r"(a) : "l"(p));
    return a;
}

__device__ __forceinline__ void bulk_copy(uint32_t dst, const void* src,
                                          uint32_t bytes, uint32_t mbar) {
    asm volatile("mbarrier.arrive.expect_tx.shared.b64 _, [%0], %1;"
                 :: "r"(mbar), "r"(bytes) : "memory");
    asm volatile(
        "cp.async.bulk.shared::cta.global.mbarrier::complete_tx::bytes "
        "[%0], [%1], %2, [%3];"
        :: "r"(dst), "l"(src), "r"(bytes), "r"(mbar) : "memory");
}

__device__ __forceinline__ void mbar_wait0(uint32_t mbar) {
    uint32_t done;
    asm volatile(
        "{\n\t.reg .pred p;\n\t"
        "mbarrier.try_wait.parity.acquire.cta.shared::cta.b64 p, [%1], 0;\n\t"
        "selp.b32 %0, 1, 0, p;\n\t}"
        : "=r"(done) : "r"(mbar) : "memory");
    if (!done) {
        asm volatile(
            "{\n\t.reg .pred P1;\n\t"
            "WL_%=:\n\t"
            "mbarrier.try_wait.parity.acquire.cta.shared::cta.b64 P1, [%0], 0, 0x989680;\n\t"
            "@P1 bra.uni WD_%=;\n\t"
            "bra.uni WL_%=;\n\t"
            "WD_%=:\n\t}"
            :: "r"(mbar) : "memory");
    }
}

__device__ __forceinline__ float sqrt_approx(float x) {
    float r;
    asm("sqrt.approx.f32 %0, %1;" : "=f"(r) : "f"(x));
    return r;
}

__global__ void __launch_bounds__(NTHREADS, 8)
prl_main_kernel(const float* __restrict__ pcs, float* __restrict__ out) {
    __shared__ alignas(128) float4 sbuf[1536];          // 24 KB, halves at 0/768
    __shared__ alignas(8) uint64_t mbar[2];
    __shared__ float s_mean[NPATCH * 3];
    __shared__ float s_std[NPATCH * 3];
    __shared__ float s_part[8];

    const int tid = threadIdx.x;
    const int lane = tid & 31;
    const int warp = tid >> 5;
    const int half = tid >> 7;          // warps 0-3 -> chunk0, 4-7 -> chunk1
    const int tl = tid & 127;
    const uint32_t mb = smem_u32(&mbar[half]);
    const uint32_t sbase = smem_u32(sbuf);

    if (tid == 0) {
        asm volatile("mbarrier.init.shared.b64 [%0], 1;" :: "r"(smem_u32(&mbar[0])) : "memory");
        asm volatile("mbarrier.init.shared.b64 [%0], 1;" :: "r"(smem_u32(&mbar[1])) : "memory");
        const char* src = reinterpret_cast<const char*>(pcs) +
                          (size_t)blockIdx.x * BATCH_BYTES;
        bulk_copy(sbase, src, CHUNK_BYTES, smem_u32(&mbar[0]));
        bulk_copy(sbase + CHUNK_BYTES, src + CHUNK_BYTES, CHUNK_BYTES,
                  smem_u32(&mbar[1]));
    }
    __syncthreads();   // mbarrier inits visible before any wait

    mbar_wait0(mb);

    // ---- Stats: thread owns f4[6*tl .. 6*tl+5] of its half (24 consecutive
    // floats, phase 0). Loads permuted by delta=(lane>>2)&1 for bank-conflict
    // freedom; delta rotates the dim frame by +delta, undone via SELs below.
    const int delta = (lane >> 2) & 1;
    // packed accumulators: pair types (d0,d1),(d2,d0),(d1,d2) in delta-frame
    uint64_t S01 = 0, S20 = 0, S12 = 0;
    uint64_t Q01 = 0, Q20 = 0, Q12 = 0;
    const uint32_t tbase = sbase + (uint32_t)half * CHUNK_BYTES + (uint32_t)tl * 96;

#pragma unroll
    for (int j = 0; j < 6; j++) {
        int m = j + delta; if (m >= 6) m -= 6;
        uint64_t plo, phi;   // plo=(e0,e1), phi=(e2,e3); f4 start phase = j mod 3 (frame)
        asm("ld.shared.v2.b64 {%0,%1}, [%2];"
            : "=l"(plo), "=l"(phi) : "r"(tbase + (uint32_t)(m * 16)));
        if (j % 3 == 0) {      // pairs (0,1),(2,0)
            asm("add.rn.f32x2 %0,%0,%1;" : "+l"(S01) : "l"(plo));
            asm("add.rn.f32x2 %0,%0,%1;" : "+l"(S20) : "l"(phi));
            asm("fma.rn.f32x2 %0,%1,%1,%0;" : "+l"(Q01) : "l"(plo));
            asm("fma.rn.f32x2 %0,%1,%1,%0;" : "+l"(Q20) : "l"(phi));
        } else if (j % 3 == 1) { // pairs (1,2),(0,1)
            asm("add.rn.f32x2 %0,%0,%1;" : "+l"(S12) : "l"(plo));
            asm("add.rn.f32x2 %0,%0,%1;" : "+l"(S01) : "l"(phi));
            asm("fma.rn.f32x2 %0,%1,%1,%0;" : "+l"(Q12) : "l"(plo));
            asm("fma.rn.f32x2 %0,%1,%1,%0;" : "+l"(Q01) : "l"(phi));
        } else {                 // pairs (2,0),(1,2)
            asm("add.rn.f32x2 %0,%0,%1;" : "+l"(S20) : "l"(plo));
            asm("add.rn.f32x2 %0,%0,%1;" : "+l"(S12) : "l"(phi));
            asm("fma.rn.f32x2 %0,%1,%1,%0;" : "+l"(Q20) : "l"(plo));
            asm("fma.rn.f32x2 %0,%1,%1,%0;" : "+l"(Q12) : "l"(phi));
        }
    }

    // unpack: frame-dim sums  f0=S01.lo+S20.hi  f1=S01.hi+S12.lo  f2=S20.lo+S12.hi
    float a0l, a0h, a1l, a1h, a2l, a2h;
    asm("mov.b64 {%0,%1}, %2;" : "=f"(a0l), "=f"(a0h) : "l"(S01));
    asm("mov.b64 {%0,%1}, %2;" : "=f"(a1l), "=f"(a1h) : "l"(S20));
    asm("mov.b64 {%0,%1}, %2;" : "=f"(a2l), "=f"(a2h) : "l"(S12));
    float fs0 = a0l + a1h, fs1 = a0h + a2l, fs2 = a1l + a2h;
    asm("mov.b64 {%0,%1}, %2;" : "=f"(a0l), "=f"(a0h) : "l"(Q01));
    asm("mov.b64 {%0,%1}, %2;" : "=f"(a1l), "=f"(a1h) : "l"(Q20));
    asm("mov.b64 {%0,%1}, %2;" : "=f"(a2l), "=f"(a2h) : "l"(Q12));
    float fq0 = a0l + a1h, fq1 = a0h + a2l, fq2 = a1l + a2h;

    // un-rotate: frame slot f holds actual dim (f+delta)%3
    float s0 = delta ? fs2 : fs0;
    float s1 = delta ? fs0 : fs1;
    float s2 = delta ? fs1 : fs2;
    float q0 = delta ? fq2 : fq0;
    float q1 = delta ? fq0 : fq1;
    float q2 = delta ? fq1 : fq2;

    // 8-lane group reduce (threads 8p..8p+7 own patch p of this half)
#pragma unroll
    for (int off = 4; off; off >>= 1) {
        s0 += __shfl_xor_sync(0xFFFFFFFFu, s0, off);
        s1 += __shfl_xor_sync(0xFFFFFFFFu, s1, off);
        s2 += __shfl_xor_sync(0xFFFFFFFFu, s2, off);
        q0 += __shfl_xor_sync(0xFFFFFFFFu, q0, off);
        q1 += __shfl_xor_sync(0xFFFFFFFFu, q1, off);
        q2 += __shfl_xor_sync(0xFFFFFFFFu, q2, off);
    }
    if ((tl & 7) == 0) {
        const int gp = half * 16 + (tl >> 3);
        const float inv_n = 1.0f / 64.0f;
        const float inv_nm1 = 1.0f / 63.0f;
        s_mean[gp * 3 + 0] = s0 * inv_n;
        s_mean[gp * 3 + 1] = s1 * inv_n;
        s_mean[gp * 3 + 2] = s2 * inv_n;
        float v0 = (q0 - s0 * s0 * inv_n) * inv_nm1;
        float v1 = (q1 - s1 * s1 * inv_n) * inv_nm1;
        float v2 = (q2 - s2 * s2 * inv_n) * inv_nm1;
        s_std[gp * 3 + 0] = sqrt_approx(fmaxf(v0, 0.0f));
        s_std[gp * 3 + 1] = sqrt_approx(fmaxf(v1, 0.0f));
        s_std[gp * 3 + 2] = sqrt_approx(fmaxf(v2, 0.0f));
    }
    __syncthreads();

    // ---- Pair phase: full 32x32 symmetric; upper-tri incl diag =
    // 0.5*full + 0.5*diag -> weight 0.5 off-diag, 1.0 on diag.
    float local = 0.0f;
#pragma unroll
    for (int k = 0; k < (NPATCH * NPATCH) / NTHREADS; k++) {
        const int id = tid + k * NTHREADS;
        const int i = id >> 5;   // uniform within warp (broadcast)
        const int j = id & 31;   // stride-3 words, conflict-free
        float acc = 0.0f;
#pragma unroll
        for (int d = 0; d < 3; d++) {
            float ssum = s_std[i * 3 + d] + s_std[j * 3 + d];
            float dmean = fabsf(s_mean[i * 3 + d] - s_mean[j * 3 + d]);
            float rep = fmaxf(ssum - dmean, 0.0f);
            acc = fmaf(rep, rep, acc);
        }
        float nrm = (acc > 0.0f) ? sqrt_approx(acc) : 0.0f;
        local += (i == j) ? nrm : 0.5f * nrm;
    }

    // ---- Block reduce + single atomic ----
#pragma unroll
    for (int off = 16; off; off >>= 1)
        local += __shfl_xor_sync(0xFFFFFFFFu, local, off);
    if (lane == 0) s_part[warp] = local;
    __syncthreads();
    if (warp == 0) {
        float v = (lane < 8) ? s_part[lane] : 0.0f;
#pragma unroll
        for (int off = 4; off; off >>= 1)
            v += __shfl_xor_sync(0xFFFFFFFFu, v, off);
        if (lane == 0) {
            const float scale = 1.0f / (528.0f * (float)NBATCH);
            atomicAdd(out, v * scale);
        }
    }
}

extern "C" void kernel_launch(void* const* d_in, const int* in_sizes, int n_in,
                              void* d_out, int out_size) {
    const float* pcs = (const float*)d_in[0];
    float* out = (float*)d_out;
    prl_zero_kernel<<<1, 1>>>(out);
    prl_main_kernel<<<NBATCH, NTHREADS>>>(pcs, out);
}

// round 5
// speedup vs baseline: 1.2797x; 1.0261x over previous
#include <cuda_runtime.h>
#include <cstdint>
#include <math.h>

// PatchRepulsionLoss: pcs [8192, 2048, 3] f32 -> scalar f32
// B=8192, P=32 patches, n=64 pts/patch, N_SIGMA=1
// loss = sum_b sum_{i<=j} || relu(std_i+std_j - |mean_i-mean_j|) ||_2 / (528*B)
//
// Pair identity: std_i+std_j - |m_i-m_j| = min(hi_j - lo_i, hi_i - lo_j),
// hi = mean+std, lo = mean-std.

#define NPATCH 32
#define NBATCH 8192
#define NTHREADS 256
#define CHUNK_BYTES 12288            // 16 patches
#define BATCH_BYTES (2 * CHUNK_BYTES)

__global__ void prl_zero_kernel(float* out) { out[0] = 0.0f; }

__device__ __forceinline__ uint32_t smem_u32(const void* p) {
    uint32_t a;
    asm("{ .reg .u64 t; cvta.to.shared.u64 t, %1; cvt.u32.u64 %0, t; }"
        : "=r"(a) : "l"(p));
    return a;
}

__device__ __forceinline__ void bulk_copy(uint32_t dst, const void* src,
                                          uint32_t bytes, uint32_t mbar) {
    asm volatile("mbarrier.arrive.expect_tx.shared.b64 _, [%0], %1;"
                 :: "r"(mbar), "r"(bytes) : "memory");
    asm volatile(
        "cp.async.bulk.shared::cta.global.mbarrier::complete_tx::bytes "
        "[%0], [%1], %2, [%3];"
        :: "r"(dst), "l"(src), "r"(bytes), "r"(mbar) : "memory");
}

__device__ __forceinline__ void mbar_wait0(uint32_t mbar) {
    uint32_t done;
    asm volatile(
        "{\n\t.reg .pred p;\n\t"
        "mbarrier.try_wait.parity.acquire.cta.shared::cta.b64 p, [%1], 0;\n\t"
        "selp.b32 %0, 1, 0, p;\n\t}"
        : "=r"(done) : "r"(mbar) : "memory");
    if (!done) {
        asm volatile(
            "{\n\t.reg .pred P1;\n\t"
            "WL_%=:\n\t"
            "mbarrier.try_wait.parity.acquire.cta.shared::cta.b64 P1, [%0], 0, 0x989680;\n\t"
            "@P1 bra.uni WD_%=;\n\t"
            "bra.uni WL_%=;\n\t"
            "WD_%=:\n\t}"
            :: "r"(mbar) : "memory");
    }
}

__device__ __forceinline__ float sqrt_approx(float x) {
    float r;
    asm("sqrt.approx.f32 %0, %1;" : "=f"(r) : "f"(x));
    return r;
}

__global__ void __launch_bounds__(NTHREADS, 8)
prl_main_kernel(const float* __restrict__ pcs, float* __restrict__ out) {
    __shared__ alignas(128) float4 sbuf[1536];          // 24 KB, halves at 0/768
    __shared__ alignas(8) uint64_t mbar[2];
    __shared__ float s_lo[3 * NPATCH];                  // SoA [d][patch]
    __shared__ float s_hi[3 * NPATCH];
    __shared__ float s_part[8];

    const int tid = threadIdx.x;
    const int lane = tid & 31;
    const int warp = tid >> 5;
    const int half = tid >> 7;          // warps 0-3 -> chunk0, 4-7 -> chunk1
    const int tl = tid & 127;
    const uint32_t mb = smem_u32(&mbar[half]);
    const uint32_t sbase = smem_u32(sbuf);

    if (tid == 0) {
        asm volatile("mbarrier.init.shared.b64 [%0], 1;" :: "r"(smem_u32(&mbar[0])) : "memory");
        asm volatile("mbarrier.init.shared.b64 [%0], 1;" :: "r"(smem_u32(&mbar[1])) : "memory");
        const char* src = reinterpret_cast<const char*>(pcs) +
                          (size_t)blockIdx.x * BATCH_BYTES;
        bulk_copy(sbase, src, CHUNK_BYTES, smem_u32(&mbar[0]));
        bulk_copy(sbase + CHUNK_BYTES, src + CHUNK_BYTES, CHUNK_BYTES,
                  smem_u32(&mbar[1]));
    }
    __syncthreads();   // mbarrier inits visible before any wait

    mbar_wait0(mb);

    // ---- Stats: thread owns f4[6*tl .. 6*tl+5] of its half (24 consecutive
    // floats, phase 0). Loads permuted by delta=(lane>>2)&1 for bank-conflict
    // freedom; delta rotates the dim frame by +delta, undone via SELs below.
    const int delta = (lane >> 2) & 1;
    // packed accumulators: pair types (d0,d1),(d2,d0),(d1,d2) in delta-frame
    uint64_t S01 = 0, S20 = 0, S12 = 0;
    uint64_t Q01 = 0, Q20 = 0, Q12 = 0;
    const uint32_t tbase = sbase + (uint32_t)half * CHUNK_BYTES + (uint32_t)tl * 96;

#pragma unroll
    for (int j = 0; j < 6; j++) {
        int m = j + delta; if (m >= 6) m -= 6;
        uint64_t plo, phi;   // plo=(e0,e1), phi=(e2,e3); f4 start phase = j mod 3 (frame)
        asm("ld.shared.v2.b64 {%0,%1}, [%2];"
            : "=l"(plo), "=l"(phi) : "r"(tbase + (uint32_t)(m * 16)));
        if (j % 3 == 0) {      // pairs (0,1),(2,0)
            asm("add.rn.f32x2 %0,%0,%1;" : "+l"(S01) : "l"(plo));
            asm("add.rn.f32x2 %0,%0,%1;" : "+l"(S20) : "l"(phi));
            asm("fma.rn.f32x2 %0,%1,%1,%0;" : "+l"(Q01) : "l"(plo));
            asm("fma.rn.f32x2 %0,%1,%1,%0;" : "+l"(Q20) : "l"(phi));
        } else if (j % 3 == 1) { // pairs (1,2),(0,1)
            asm("add.rn.f32x2 %0,%0,%1;" : "+l"(S12) : "l"(plo));
            asm("add.rn.f32x2 %0,%0,%1;" : "+l"(S01) : "l"(phi));
            asm("fma.rn.f32x2 %0,%1,%1,%0;" : "+l"(Q12) : "l"(plo));
            asm("fma.rn.f32x2 %0,%1,%1,%0;" : "+l"(Q01) : "l"(phi));
        } else {                 // pairs (2,0),(1,2)
            asm("add.rn.f32x2 %0,%0,%1;" : "+l"(S20) : "l"(plo));
            asm("add.rn.f32x2 %0,%0,%1;" : "+l"(S12) : "l"(phi));
            asm("fma.rn.f32x2 %0,%1,%1,%0;" : "+l"(Q20) : "l"(plo));
            asm("fma.rn.f32x2 %0,%1,%1,%0;" : "+l"(Q12) : "l"(phi));
        }
    }

    // unpack: frame-dim sums  f0=S01.lo+S20.hi  f1=S01.hi+S12.lo  f2=S20.lo+S12.hi
    float a0l, a0h, a1l, a1h, a2l, a2h;
    asm("mov.b64 {%0,%1}, %2;" : "=f"(a0l), "=f"(a0h) : "l"(S01));
    asm("mov.b64 {%0,%1}, %2;" : "=f"(a1l), "=f"(a1h) : "l"(S20));
    asm("mov.b64 {%0,%1}, %2;" : "=f"(a2l), "=f"(a2h) : "l"(S12));
    float fs0 = a0l + a1h, fs1 = a0h + a2l, fs2 = a1l + a2h;
    asm("mov.b64 {%0,%1}, %2;" : "=f"(a0l), "=f"(a0h) : "l"(Q01));
    asm("mov.b64 {%0,%1}, %2;" : "=f"(a1l), "=f"(a1h) : "l"(Q20));
    asm("mov.b64 {%0,%1}, %2;" : "=f"(a2l), "=f"(a2h) : "l"(Q12));
    float fq0 = a0l + a1h, fq1 = a0h + a2l, fq2 = a1l + a2h;

    // un-rotate: frame slot f holds actual dim (f+delta)%3
    float s0 = delta ? fs2 : fs0;
    float s1 = delta ? fs0 : fs1;
    float s2 = delta ? fs1 : fs2;
    float q0 = delta ? fq2 : fq0;
    float q1 = delta ? fq0 : fq1;
    float q2 = delta ? fq1 : fq2;

    // 8-lane group reduce (threads 8p..8p+7 own patch p of this half)
#pragma unroll
    for (int off = 4; off; off >>= 1) {
        s0 += __shfl_xor_sync(0xFFFFFFFFu, s0, off);
        s1 += __shfl_xor_sync(0xFFFFFFFFu, s1, off);
        s2 += __shfl_xor_sync(0xFFFFFFFFu, s2, off);
        q0 += __shfl_xor_sync(0xFFFFFFFFu, q0, off);
        q1 += __shfl_xor_sync(0xFFFFFFFFu, q1, off);
        q2 += __shfl_xor_sync(0xFFFFFFFFu, q2, off);
    }
    if ((tl & 7) == 0) {
        const int gp = half * 16 + (tl >> 3);
        const float inv_n = 1.0f / 64.0f;
        const float inv_nm1 = 1.0f / 63.0f;
        float m0 = s0 * inv_n, m1 = s1 * inv_n, m2 = s2 * inv_n;
        float sd0 = sqrt_approx(fmaxf((q0 - s0 * m0) * inv_nm1, 0.0f));
        float sd1 = sqrt_approx(fmaxf((q1 - s1 * m1) * inv_nm1, 0.0f));
        float sd2 = sqrt_approx(fmaxf((q2 - s2 * m2) * inv_nm1, 0.0f));
        s_lo[0 * NPATCH + gp] = m0 - sd0;
        s_lo[1 * NPATCH + gp] = m1 - sd1;
        s_lo[2 * NPATCH + gp] = m2 - sd2;
        s_hi[0 * NPATCH + gp] = m0 + sd0;
        s_hi[1 * NPATCH + gp] = m1 + sd1;
        s_hi[2 * NPATCH + gp] = m2 + sd2;
    }
    __syncthreads();

    // ---- Pair phase: full 32x32 symmetric; upper-tri incl diag =
    // 0.5*full + 0.5*diag -> weight 0.5 off-diag, 1.0 on diag.
    // j = lane stats hoisted to registers; i = warp + 8k uniform (broadcast LDS).
    const float jlo0 = s_lo[0 * NPATCH + lane];
    const float jlo1 = s_lo[1 * NPATCH + lane];
    const float jlo2 = s_lo[2 * NPATCH + lane];
    const float jhi0 = s_hi[0 * NPATCH + lane];
    const float jhi1 = s_hi[1 * NPATCH + lane];
    const float jhi2 = s_hi[2 * NPATCH + lane];

    float local = 0.0f;
#pragma unroll
    for (int k = 0; k < 4; k++) {
        const int i = warp + 8 * k;          // uniform within warp
        const float ilo0 = s_lo[0 * NPATCH + i];
        const float ilo1 = s_lo[1 * NPATCH + i];
        const float ilo2 = s_lo[2 * NPATCH + i];
        const float ihi0 = s_hi[0 * NPATCH + i];
        const float ihi1 = s_hi[1 * NPATCH + i];
        const float ihi2 = s_hi[2 * NPATCH + i];
        float r0 = fmaxf(fminf(ihi0 - jlo0, jhi0 - ilo0), 0.0f);
        float r1 = fmaxf(fminf(ihi1 - jlo1, jhi1 - ilo1), 0.0f);
        float r2 = fmaxf(fminf(ihi2 - jlo2, jhi2 - ilo2), 0.0f);
        float acc = fmaf(r0, r0, fmaf(r1, r1, r2 * r2));
        float nrm = sqrt_approx(acc);
        local += (i == lane) ? nrm : 0.5f * nrm;
    }

    // ---- Block reduce + single atomic ----
#pragma unroll
    for (int off = 16; off; off >>= 1)
        local += __shfl_xor_sync(0xFFFFFFFFu, local, off);
    if (lane == 0) s_part[warp] = local;
    __syncthreads();
    if (warp == 0) {
        float v = (lane < 8) ? s_part[lane] : 0.0f;
#pragma unroll
        for (int off = 4; off; off >>= 1)
            v += __shfl_xor_sync(0xFFFFFFFFu, v, off);
        if (lane == 0) {
            const float scale = 1.0f / (528.0f * (float)NBATCH);
            atomicAdd(out, v * scale);
        }
    }
}

extern "C" void kernel_launch(void* const* d_in, const int* in_sizes, int n_in,
                              void* d_out, int out_size) {
    const float* pcs = (const float*)d_in[0];
    float* out = (float*)d_out;
    prl_zero_kernel<<<1, 1>>>(out);
    prl_main_kernel<<<NBATCH, NTHREADS>>>(pcs, out);
}